// round 12
// baseline (speedup 1.0000x reference)
#include <cuda_runtime.h>
#include <cuda_bf16.h>
#include <cstdint>
#include <math.h>

// ---------------- problem dims ----------------
#define BATCH 4
#define SEQ   2048
#define EMB   1024
#define NHEAD 16
#define HSZ   64
#define MTOT  (BATCH * SEQ)   // 8192

// q pre-scale: (1/sqrt(64)) * log2(e)  -> softmax done in exp2 domain
#define QSCALE 0.1803368801111204f

// ---------------- device scratch (no runtime allocation) ----------------
__device__ __align__(128) uint32_t g_q[(size_t)BATCH * NHEAD * SEQ * HSZ];
__device__ __align__(128) uint32_t g_k[(size_t)BATCH * NHEAD * SEQ * HSZ];
__device__ __align__(128) uint32_t g_v[(size_t)BATCH * NHEAD * SEQ * HSZ];
__device__ __align__(128) uint32_t g_y[(size_t)MTOT * EMB];
__device__ __align__(128) uint32_t g_xt[(size_t)MTOT * EMB];
__device__ __align__(128) uint32_t g_wt[(size_t)4 * EMB * EMB];

// ---------------- helpers ----------------
__device__ __forceinline__ uint32_t f2tf32(float f) {
    uint32_t r;
    asm("cvt.rna.tf32.f32 %0, %1;" : "=r"(r) : "f"(f));
    return r;
}
__device__ __forceinline__ float ex2(float x) {
    float r;
    asm("ex2.approx.f32 %0, %1;" : "=f"(r) : "f"(x));
    return r;
}

__device__ __forceinline__ void mma_tf32(float* d, const uint32_t* a, const uint32_t* b) {
    asm volatile(
        "mma.sync.aligned.m16n8k8.row.col.f32.tf32.tf32.f32 "
        "{%0,%1,%2,%3}, {%4,%5,%6,%7}, {%8,%9}, {%0,%1,%2,%3};"
        : "+f"(d[0]), "+f"(d[1]), "+f"(d[2]), "+f"(d[3])
        : "r"(a[0]), "r"(a[1]), "r"(a[2]), "r"(a[3]), "r"(b[0]), "r"(b[1]));
}

__device__ __forceinline__ void cp16(uint32_t sdst, const void* gsrc) {
    asm volatile("cp.async.cg.shared.global [%0], [%1], 16;" :: "r"(sdst), "l"(gsrc));
}
__device__ __forceinline__ void cp_commit() {
    asm volatile("cp.async.commit_group;" ::: "memory");
}
template <int N>
__device__ __forceinline__ void cp_wait() {
    asm volatile("cp.async.wait_group %0;" :: "n"(N) : "memory");
}

// =============================================================
// fused converter: fp32 -> tf32 bits for x and all four W matrices.
// Flat index in float4 units: [0, NX) -> x, then 4 x NW -> W0..W3.
// =============================================================
#define NX ((size_t)MTOT * EMB / 4)
#define NW ((size_t)EMB * EMB / 4)

__global__ __launch_bounds__(256) void convert_all_kernel(
    const float* __restrict__ x,
    const float* __restrict__ W0, const float* __restrict__ W1,
    const float* __restrict__ W2, const float* __restrict__ W3)
{
    const size_t idx = (size_t)blockIdx.x * 256 + threadIdx.x;
    const float* src;
    uint32_t* dst;
    size_t off;
    if (idx < NX) {
        src = x; dst = g_xt; off = idx * 4;
    } else {
        const size_t j = idx - NX;
        const int mat = (int)(j >> 18);          // / (EMB*EMB/4) = 262144
        off = (j & (NW - 1)) * 4;
        src = (mat == 0) ? W0 : (mat == 1) ? W1 : (mat == 2) ? W2 : W3;
        dst = g_wt + (size_t)mat * EMB * EMB;
    }
    float4 v = *(const float4*)(src + off);
    uint4 t;
    t.x = f2tf32(v.x); t.y = f2tf32(v.y); t.z = f2tf32(v.z); t.w = f2tf32(v.w);
    *(uint4*)(dst + off) = t;
}

// ---------------- GEMM config ----------------
#define APAD 36
#define BPAD 136
#define ABUF (128 * APAD)
#define BBUF (32 * BPAD)
#define GEMM_SMEM_BYTES ((2 * ABUF + 2 * BBUF + 128) * 4)

// =============================================================
// tf32 mma.sync GEMM, cp.async pipelined; 3 CTAs/SM (reg cap 170).
// =============================================================
template <int MODE>
__global__ __launch_bounds__(128, 3) void gemm_kernel(
    const float* __restrict__ bias0, const float* __restrict__ bias1,
    const float* __restrict__ bias2, float* __restrict__ outp)
{
    extern __shared__ uint32_t dynsm[];
    uint32_t* As = dynsm;
    uint32_t* Bs = dynsm + 2 * ABUF;
    float* bias_s = (float*)(dynsm + 2 * ABUF + 2 * BBUF);

    const int tid  = threadIdx.x;
    const int wid  = tid >> 5;
    const int lane = tid & 31;
    const int g    = lane >> 2;
    const int qd   = lane & 3;
    const int wm   = (wid >> 1) * 64;
    const int wn   = (wid & 1) * 64;
    const int n0   = blockIdx.x * 128;
    const int m0   = blockIdx.y * 128;
    const int mat  = (MODE == 0) ? (int)blockIdx.z : 3;

    const uint32_t* A = (MODE == 0) ? g_xt : g_y;
    const uint32_t* W = g_wt + (size_t)mat * EMB * EMB;
    const float* bias = (MODE == 0) ? ((mat == 0) ? bias0 : (mat == 1) ? bias1 : bias2)
                                    : bias0;

    bias_s[tid] = bias[n0 + tid];

    const uint32_t sA = (uint32_t)__cvta_generic_to_shared(As);
    const uint32_t sB = (uint32_t)__cvta_generic_to_shared(Bs);

    const int a_row = tid >> 3;
    const int a_kq  = tid & 7;
    const int b_kr  = tid >> 5;
    const int b_nq  = tid & 31;

    #define ISSUE_CHUNK(K0, BUF) do { \
        const uint32_t sAb = sA + (BUF) * (ABUF * 4); \
        const uint32_t sBb = sB + (BUF) * (BBUF * 4); \
        _Pragma("unroll") \
        for (int it = 0; it < 8; ++it) { \
            const int ar = it * 16 + a_row; \
            cp16(sAb + (ar * APAD + a_kq * 4) * 4, \
                 A + (size_t)(m0 + ar) * EMB + (K0) + a_kq * 4); \
            const int br = it * 4 + b_kr; \
            cp16(sBb + (br * BPAD + b_nq * 4) * 4, \
                 W + (size_t)((K0) + br) * EMB + n0 + b_nq * 4); \
        } \
    } while (0)

    float acc[4][8][4];
    #pragma unroll
    for (int i = 0; i < 4; i++)
        #pragma unroll
        for (int j = 0; j < 8; j++)
            #pragma unroll
            for (int c = 0; c < 4; c++) acc[i][j][c] = 0.f;

    ISSUE_CHUNK(0, 0);
    cp_commit();

    for (int c = 0; c < EMB / 32; ++c) {
        if (c + 1 < EMB / 32) {
            ISSUE_CHUNK((c + 1) * 32, (c + 1) & 1);
            cp_commit();
        }
        if (c + 1 < EMB / 32) cp_wait<1>(); else cp_wait<0>();
        __syncthreads();

        const uint32_t* Ab = As + (c & 1) * ABUF;
        const uint32_t* Bb = Bs + (c & 1) * BBUF;

        #pragma unroll
        for (int ks = 0; ks < 4; ++ks) {
            const int kk = ks * 8 + qd;
            uint32_t af[4][4], bf[8][2];
            #pragma unroll
            for (int mt = 0; mt < 4; ++mt) {
                const int r = wm + mt * 16 + g;
                af[mt][0] = Ab[r * APAD + kk];
                af[mt][1] = Ab[(r + 8) * APAD + kk];
                af[mt][2] = Ab[r * APAD + kk + 4];
                af[mt][3] = Ab[(r + 8) * APAD + kk + 4];
            }
            #pragma unroll
            for (int nt = 0; nt < 8; ++nt) {
                const int n = wn + nt * 8 + g;
                bf[nt][0] = Bb[kk * BPAD + n];
                bf[nt][1] = Bb[(kk + 4) * BPAD + n];
            }
            #pragma unroll
            for (int mt = 0; mt < 4; ++mt)
                #pragma unroll
                for (int nt = 0; nt < 8; ++nt)
                    mma_tf32(acc[mt][nt], af[mt], bf[nt]);
        }
        __syncthreads();
    }
    #undef ISSUE_CHUNK

    #pragma unroll
    for (int mt = 0; mt < 4; ++mt) {
        #pragma unroll
        for (int ci = 0; ci < 2; ++ci) {
            const int m = m0 + wm + mt * 16 + g + ci * 8;
            #pragma unroll
            for (int nt = 0; nt < 8; ++nt) {
                const int nl = wn + nt * 8 + qd * 2;
                const int n  = n0 + nl;
                float vx = acc[mt][nt][ci * 2 + 0] + bias_s[nl];
                float vy = acc[mt][nt][ci * 2 + 1] + bias_s[nl + 1];
                if (MODE == 0) {
                    if (mat == 0) { vx *= QSCALE; vy *= QSCALE; }
                    const int b = m >> 11;
                    const int t = m & (SEQ - 1);
                    const int h = n >> 6;
                    const int d = n & (HSZ - 1);
                    uint32_t* dst = (mat == 0) ? g_q : (mat == 1) ? g_k : g_v;
                    uint2 o;
                    o.x = f2tf32(vx); o.y = f2tf32(vy);
                    *(uint2*)(dst + ((((size_t)b * NHEAD + h) * SEQ) + t) * HSZ + d) = o;
                } else {
                    float2 o; o.x = vx; o.y = vy;
                    *(float2*)(outp + (size_t)m * EMB + n) = o;
                }
            }
        }
    }
}

// =============================================================
// tensor-core causal flash attention v4 (exp2 domain, Ps smem transpose).
// CTA: 128 queries, 128 threads = 4 warps x 32 queries.
// =============================================================
#define KSTRIDE 68
#define VSTRIDE 72
#define KVBUF_K (64 * KSTRIDE)
#define KVBUF_V (64 * VSTRIDE)
#define PSWARP  (32 * KSTRIDE)
#define ATT_SMEM_BYTES ((2 * KVBUF_K + 2 * KVBUF_V + 4 * PSWARP) * 4)   // 106496

__global__ __launch_bounds__(128, 2) void attn_mma_kernel()
{
    extern __shared__ uint32_t sm[];
    uint32_t* KsBase = sm;
    uint32_t* VsBase = sm + 2 * KVBUF_K;
    uint32_t* Psall  = sm + 2 * KVBUF_K + 2 * KVBUF_V;
    const int tid  = threadIdx.x;
    const int wid  = tid >> 5;
    const int lane = tid & 31;
    const int g    = lane >> 2;
    const int qd   = lane & 3;
    uint32_t* Ps = Psall + wid * PSWARP;      // [32][KSTRIDE] per warp

    const int bh = blockIdx.y;
    const int q0 = (gridDim.x - 1 - blockIdx.x) * 128;
    const int wq = wid * 32;
    const size_t base = (size_t)bh * SEQ * HSZ;
    const uint32_t* Qp = g_q + base;
    const uint32_t* Kp = g_k + base;
    const uint32_t* Vp = g_v + base;

    const uint32_t sK = (uint32_t)__cvta_generic_to_shared(KsBase);
    const uint32_t sV = (uint32_t)__cvta_generic_to_shared(VsBase);

    const int l_row = tid >> 4;
    const int l_c4  = tid & 15;

    #define ISSUE_TILE(KB, BUF) do { \
        const uint32_t sKb = sK + (BUF) * (KVBUF_K * 4); \
        const uint32_t sVb = sV + (BUF) * (KVBUF_V * 4); \
        _Pragma("unroll") \
        for (int it = 0; it < 8; ++it) { \
            const int row = it * 8 + l_row; \
            cp16(sKb + (row * KSTRIDE + l_c4 * 4) * 4, \
                 Kp + (size_t)((KB) + row) * HSZ + l_c4 * 4); \
            cp16(sVb + (row * VSTRIDE + l_c4 * 4) * 4, \
                 Vp + (size_t)((KB) + row) * HSZ + l_c4 * 4); \
        } \
    } while (0)

    ISSUE_TILE(0, 0);
    cp_commit();

    // ---- stage Q (pre-scaled tf32 bits) through KV buffer 1 ----
    uint32_t* Kst = KsBase + KVBUF_K;
    uint32_t* Vst = VsBase + KVBUF_V;
    #pragma unroll
    for (int it = 0; it < 16; ++it) {
        const int row = it * 8 + l_row;
        uint4 v = *(const uint4*)(Qp + (size_t)(q0 + row) * HSZ + l_c4 * 4);
        if (row < 64) *(uint4*)&Kst[row * KSTRIDE + l_c4 * 4] = v;
        else          *(uint4*)&Vst[(row - 64) * VSTRIDE + l_c4 * 4] = v;
    }
    __syncthreads();

    uint32_t qf[2][8][4];
    {
        const uint32_t* qbuf = (wq < 64) ? Kst : Vst;
        const int qs = (wq < 64) ? KSTRIDE : VSTRIDE;
        #pragma unroll
        for (int mt = 0; mt < 2; ++mt) {
            const int r = (wq & 63) + mt * 16 + g;
            #pragma unroll
            for (int ks = 0; ks < 8; ++ks) {
                qf[mt][ks][0] = qbuf[r * qs + ks * 8 + qd];
                qf[mt][ks][1] = qbuf[(r + 8) * qs + ks * 8 + qd];
                qf[mt][ks][2] = qbuf[r * qs + ks * 8 + qd + 4];
                qf[mt][ks][3] = qbuf[(r + 8) * qs + ks * 8 + qd + 4];
            }
        }
    }
    __syncthreads();   // Q consumed before tile 1 overwrites buffer 1

    float of[2][8][4];
    #pragma unroll
    for (int mt = 0; mt < 2; ++mt)
        #pragma unroll
        for (int nt = 0; nt < 8; ++nt)
            #pragma unroll
            for (int c = 0; c < 4; ++c) of[mt][nt][c] = 0.f;
    float mx[4] = {-1e30f, -1e30f, -1e30f, -1e30f};
    float li[4] = {0.f, 0.f, 0.f, 0.f};

    const int ntile = (q0 >> 6) + 2;
    const int wrow = q0 + wq;
    for (int kt = 0; kt < ntile; ++kt) {
        const int kb = kt * 64;
        if (kt + 1 < ntile) {
            ISSUE_TILE((kt + 1) * 64, (kt + 1) & 1);
            cp_commit();
        }
        if (kt + 1 < ntile) cp_wait<1>(); else cp_wait<0>();
        __syncthreads();

        const bool active = (kb <= wrow + 31);
        if (active) {
            const uint32_t* Ks = KsBase + (kt & 1) * KVBUF_K;
            const uint32_t* Vs = VsBase + (kt & 1) * KVBUF_V;
            const bool need_mask = (kb + 63 > wrow);

            // ---- S = Q K^T (scores already in log2 domain via QSCALE) ----
            float sf[2][8][4];
            #pragma unroll
            for (int nt = 0; nt < 8; ++nt) {
                float s0[4] = {0.f, 0.f, 0.f, 0.f};
                float s1[4] = {0.f, 0.f, 0.f, 0.f};
                #pragma unroll
                for (int ks = 0; ks < 8; ++ks) {
                    uint32_t bf[2];
                    bf[0] = Ks[(nt * 8 + g) * KSTRIDE + ks * 8 + qd];
                    bf[1] = Ks[(nt * 8 + g) * KSTRIDE + ks * 8 + qd + 4];
                    mma_tf32(s0, qf[0][ks], bf);
                    mma_tf32(s1, qf[1][ks], bf);
                }
                if (need_mask) {
                    const int kl = kb + nt * 8 + 2 * qd;
                    const int r0 = wrow + g;
                    if (kl     > r0)      s0[0] = -1e30f;
                    if (kl + 1 > r0)      s0[1] = -1e30f;
                    if (kl     > r0 + 8)  s0[2] = -1e30f;
                    if (kl + 1 > r0 + 8)  s0[3] = -1e30f;
                    if (kl     > r0 + 16) s1[0] = -1e30f;
                    if (kl + 1 > r0 + 16) s1[1] = -1e30f;
                    if (kl     > r0 + 24) s1[2] = -1e30f;
                    if (kl + 1 > r0 + 24) s1[3] = -1e30f;
                }
                #pragma unroll
                for (int c = 0; c < 4; ++c) { sf[0][nt][c] = s0[c]; sf[1][nt][c] = s1[c]; }
            }

            // ---- online softmax in exp2 domain ----
            #pragma unroll
            for (int mt = 0; mt < 2; ++mt) {
                float t0 = -1e30f, t1 = -1e30f;
                #pragma unroll
                for (int nt = 0; nt < 8; ++nt) {
                    t0 = fmaxf(t0, fmaxf(sf[mt][nt][0], sf[mt][nt][1]));
                    t1 = fmaxf(t1, fmaxf(sf[mt][nt][2], sf[mt][nt][3]));
                }
                t0 = fmaxf(t0, __shfl_xor_sync(0xffffffffu, t0, 1));
                t0 = fmaxf(t0, __shfl_xor_sync(0xffffffffu, t0, 2));
                t1 = fmaxf(t1, __shfl_xor_sync(0xffffffffu, t1, 1));
                t1 = fmaxf(t1, __shfl_xor_sync(0xffffffffu, t1, 2));

                const float mn0 = fmaxf(mx[mt * 2 + 0], t0);
                const float mn1 = fmaxf(mx[mt * 2 + 1], t1);
                const float cr0 = ex2(mx[mt * 2 + 0] - mn0);
                const float cr1 = ex2(mx[mt * 2 + 1] - mn1);
                mx[mt * 2 + 0] = mn0;
                mx[mt * 2 + 1] = mn1;

                float ps0 = 0.f, ps1 = 0.f;
                #pragma unroll
                for (int nt = 0; nt < 8; ++nt) {
                    sf[mt][nt][0] = ex2(sf[mt][nt][0] - mn0);
                    sf[mt][nt][1] = ex2(sf[mt][nt][1] - mn0);
                    sf[mt][nt][2] = ex2(sf[mt][nt][2] - mn1);
                    sf[mt][nt][3] = ex2(sf[mt][nt][3] - mn1);
                    ps0 += sf[mt][nt][0] + sf[mt][nt][1];
                    ps1 += sf[mt][nt][2] + sf[mt][nt][3];
                }
                ps0 += __shfl_xor_sync(0xffffffffu, ps0, 1);
                ps0 += __shfl_xor_sync(0xffffffffu, ps0, 2);
                ps1 += __shfl_xor_sync(0xffffffffu, ps1, 1);
                ps1 += __shfl_xor_sync(0xffffffffu, ps1, 2);
                li[mt * 2 + 0] = li[mt * 2 + 0] * cr0 + ps0;
                li[mt * 2 + 1] = li[mt * 2 + 1] * cr1 + ps1;

                #pragma unroll
                for (int nt = 0; nt < 8; ++nt) {
                    of[mt][nt][0] *= cr0; of[mt][nt][1] *= cr0;
                    of[mt][nt][2] *= cr1; of[mt][nt][3] *= cr1;
                }
            }

            // ---- P (tf32) -> per-warp smem transpose ----
            #pragma unroll
            for (int mt = 0; mt < 2; ++mt) {
                #pragma unroll
                for (int nt = 0; nt < 8; ++nt) {
                    uint2 a, b;
                    a.x = f2tf32(sf[mt][nt][0]); a.y = f2tf32(sf[mt][nt][1]);
                    b.x = f2tf32(sf[mt][nt][2]); b.y = f2tf32(sf[mt][nt][3]);
                    *(uint2*)&Ps[(mt * 16 + g) * KSTRIDE + nt * 8 + 2 * qd] = a;
                    *(uint2*)&Ps[(mt * 16 + g + 8) * KSTRIDE + nt * 8 + 2 * qd] = b;
                }
            }
            __syncwarp();

            // ---- O += P V (A-frags from Ps, conflict-free banks 4g+qd) ----
            #pragma unroll
            for (int ks = 0; ks < 8; ++ks) {
                uint32_t af0[4], af1[4];
                af0[0] = Ps[(g)      * KSTRIDE + ks * 8 + qd];
                af0[1] = Ps[(g + 8)  * KSTRIDE + ks * 8 + qd];
                af0[2] = Ps[(g)      * KSTRIDE + ks * 8 + qd + 4];
                af0[3] = Ps[(g + 8)  * KSTRIDE + ks * 8 + qd + 4];
                af1[0] = Ps[(16 + g)     * KSTRIDE + ks * 8 + qd];
                af1[1] = Ps[(16 + g + 8) * KSTRIDE + ks * 8 + qd];
                af1[2] = Ps[(16 + g)     * KSTRIDE + ks * 8 + qd + 4];
                af1[3] = Ps[(16 + g + 8) * KSTRIDE + ks * 8 + qd + 4];
                #pragma unroll
                for (int nt = 0; nt < 8; ++nt) {
                    uint32_t bf[2];
                    bf[0] = Vs[(ks * 8 + qd) * VSTRIDE + nt * 8 + g];
                    bf[1] = Vs[(ks * 8 + qd + 4) * VSTRIDE + nt * 8 + g];
                    mma_tf32(of[0][nt], af0, bf);
                    mma_tf32(of[1][nt], af1, bf);
                }
            }
        }
        __syncthreads();
    }
    #undef ISSUE_TILE

    // ---- epilogue ----
    const int b = bh / NHEAD;
    const int h = bh % NHEAD;
    #pragma unroll
    for (int mt = 0; mt < 2; ++mt) {
        const float inv0 = 1.f / li[mt * 2 + 0];
        const float inv1 = 1.f / li[mt * 2 + 1];
        const int r0 = wrow + mt * 16 + g;
        uint32_t* y0 = g_y + ((size_t)b * SEQ + r0) * EMB + h * HSZ;
        uint32_t* y1 = g_y + ((size_t)b * SEQ + r0 + 8) * EMB + h * HSZ;
        #pragma unroll
        for (int nt = 0; nt < 8; ++nt) {
            uint2 o0, o1;
            o0.x = f2tf32(of[mt][nt][0] * inv0); o0.y = f2tf32(of[mt][nt][1] * inv0);
            o1.x = f2tf32(of[mt][nt][2] * inv1); o1.y = f2tf32(of[mt][nt][3] * inv1);
            *(uint2*)(y0 + nt * 8 + 2 * qd) = o0;
            *(uint2*)(y1 + nt * 8 + 2 * qd) = o1;
        }
    }
}

// =============================================================
extern "C" void kernel_launch(void* const* d_in, const int* in_sizes, int n_in,
                              void* d_out, int out_size)
{
    const float* x  = (const float*)d_in[0];
    const float* Wq = (const float*)d_in[1];
    const float* bq = (const float*)d_in[2];
    const float* Wk = (const float*)d_in[3];
    const float* bk = (const float*)d_in[4];
    const float* Wv = (const float*)d_in[5];
    const float* bv = (const float*)d_in[6];
    const float* Wo = (const float*)d_in[7];
    const float* bo = (const float*)d_in[8];
    float* out = (float*)d_out;

    cudaFuncSetAttribute(gemm_kernel<0>, cudaFuncAttributeMaxDynamicSharedMemorySize,
                         GEMM_SMEM_BYTES);
    cudaFuncSetAttribute(gemm_kernel<1>, cudaFuncAttributeMaxDynamicSharedMemorySize,
                         GEMM_SMEM_BYTES);
    cudaFuncSetAttribute(attn_mma_kernel, cudaFuncAttributeMaxDynamicSharedMemorySize,
                         ATT_SMEM_BYTES);

    const int conv_blocks = (int)((NX + 4 * NW) / 256);
    convert_all_kernel<<<conv_blocks, 256>>>(x, Wq, Wk, Wv, Wo);

    dim3 qkv_grid(EMB / 128, MTOT / 128, 3);
    gemm_kernel<0><<<qkv_grid, 128, GEMM_SMEM_BYTES>>>(bq, bk, bv, nullptr);

    dim3 attn_grid(SEQ / 128, BATCH * NHEAD);
    attn_mma_kernel<<<attn_grid, 128, ATT_SMEM_BYTES>>>();

    dim3 oproj_grid(EMB / 128, MTOT / 128);
    gemm_kernel<1><<<oproj_grid, 128, GEMM_SMEM_BYTES>>>(bo, nullptr, nullptr, out);
}

// round 13
// speedup vs baseline: 1.0129x; 1.0129x over previous
#include <cuda_runtime.h>
#include <cuda_bf16.h>
#include <cstdint>
#include <math.h>

// ---------------- problem dims ----------------
#define BATCH 4
#define SEQ   2048
#define EMB   1024
#define NHEAD 16
#define HSZ   64
#define MTOT  (BATCH * SEQ)   // 8192

// q pre-scale: (1/sqrt(64)) * log2(e)  -> softmax done in exp2 domain
#define QSCALE 0.1803368801111204f

// ---------------- device scratch (no runtime allocation) ----------------
__device__ __align__(128) uint32_t g_q[(size_t)BATCH * NHEAD * SEQ * HSZ];
__device__ __align__(128) uint32_t g_k[(size_t)BATCH * NHEAD * SEQ * HSZ];
__device__ __align__(128) uint32_t g_v[(size_t)BATCH * NHEAD * SEQ * HSZ];
__device__ __align__(128) uint32_t g_y[(size_t)MTOT * EMB];
__device__ __align__(128) uint32_t g_xt[(size_t)MTOT * EMB];
__device__ __align__(128) uint32_t g_wt[(size_t)4 * EMB * EMB];

// ---------------- helpers ----------------
__device__ __forceinline__ uint32_t f2tf32(float f) {
    uint32_t r;
    asm("cvt.rna.tf32.f32 %0, %1;" : "=r"(r) : "f"(f));
    return r;
}
__device__ __forceinline__ float ex2(float x) {
    float r;
    asm("ex2.approx.f32 %0, %1;" : "=f"(r) : "f"(x));
    return r;
}

__device__ __forceinline__ void mma_tf32(float* d, const uint32_t* a, const uint32_t* b) {
    asm volatile(
        "mma.sync.aligned.m16n8k8.row.col.f32.tf32.tf32.f32 "
        "{%0,%1,%2,%3}, {%4,%5,%6,%7}, {%8,%9}, {%0,%1,%2,%3};"
        : "+f"(d[0]), "+f"(d[1]), "+f"(d[2]), "+f"(d[3])
        : "r"(a[0]), "r"(a[1]), "r"(a[2]), "r"(a[3]), "r"(b[0]), "r"(b[1]));
}

__device__ __forceinline__ void cp16(uint32_t sdst, const void* gsrc) {
    asm volatile("cp.async.cg.shared.global [%0], [%1], 16;" :: "r"(sdst), "l"(gsrc));
}
__device__ __forceinline__ void cp_commit() {
    asm volatile("cp.async.commit_group;" ::: "memory");
}
template <int N>
__device__ __forceinline__ void cp_wait() {
    asm volatile("cp.async.wait_group %0;" :: "n"(N) : "memory");
}

// =============================================================
// fused converter: fp32 -> tf32 bits for x and the four W matrices.
// =============================================================
#define NX ((size_t)MTOT * EMB / 4)
#define NW ((size_t)EMB * EMB / 4)

__global__ __launch_bounds__(256) void convert_all_kernel(
    const float* __restrict__ x,
    const float* __restrict__ W0, const float* __restrict__ W1,
    const float* __restrict__ W2, const float* __restrict__ W3)
{
    const size_t idx = (size_t)blockIdx.x * 256 + threadIdx.x;
    const float* src;
    uint32_t* dst;
    size_t off;
    if (idx < NX) {
        src = x; dst = g_xt; off = idx * 4;
    } else {
        const size_t j = idx - NX;
        const int mat = (int)(j >> 18);
        off = (j & (NW - 1)) * 4;
        src = (mat == 0) ? W0 : (mat == 1) ? W1 : (mat == 2) ? W2 : W3;
        dst = g_wt + (size_t)mat * EMB * EMB;
    }
    float4 v = *(const float4*)(src + off);
    uint4 t;
    t.x = f2tf32(v.x); t.y = f2tf32(v.y); t.z = f2tf32(v.z); t.w = f2tf32(v.w);
    *(uint4*)(dst + off) = t;
}

// ---------------- GEMM config (unchanged from round 12) ----------------
#define APAD 36
#define BPAD 136
#define ABUF (128 * APAD)
#define BBUF (32 * BPAD)
#define GEMM_SMEM_BYTES ((2 * ABUF + 2 * BBUF + 128) * 4)

template <int MODE>
__global__ __launch_bounds__(128, 3) void gemm_kernel(
    const float* __restrict__ bias0, const float* __restrict__ bias1,
    const float* __restrict__ bias2, float* __restrict__ outp)
{
    extern __shared__ uint32_t dynsm[];
    uint32_t* As = dynsm;
    uint32_t* Bs = dynsm + 2 * ABUF;
    float* bias_s = (float*)(dynsm + 2 * ABUF + 2 * BBUF);

    const int tid  = threadIdx.x;
    const int wid  = tid >> 5;
    const int lane = tid & 31;
    const int g    = lane >> 2;
    const int qd   = lane & 3;
    const int wm   = (wid >> 1) * 64;
    const int wn   = (wid & 1) * 64;
    const int n0   = blockIdx.x * 128;
    const int m0   = blockIdx.y * 128;
    const int mat  = (MODE == 0) ? (int)blockIdx.z : 3;

    const uint32_t* A = (MODE == 0) ? g_xt : g_y;
    const uint32_t* W = g_wt + (size_t)mat * EMB * EMB;
    const float* bias = (MODE == 0) ? ((mat == 0) ? bias0 : (mat == 1) ? bias1 : bias2)
                                    : bias0;

    bias_s[tid] = bias[n0 + tid];

    const uint32_t sA = (uint32_t)__cvta_generic_to_shared(As);
    const uint32_t sB = (uint32_t)__cvta_generic_to_shared(Bs);

    const int a_row = tid >> 3;
    const int a_kq  = tid & 7;
    const int b_kr  = tid >> 5;
    const int b_nq  = tid & 31;

    #define ISSUE_CHUNK(K0, BUF) do { \
        const uint32_t sAb = sA + (BUF) * (ABUF * 4); \
        const uint32_t sBb = sB + (BUF) * (BBUF * 4); \
        _Pragma("unroll") \
        for (int it = 0; it < 8; ++it) { \
            const int ar = it * 16 + a_row; \
            cp16(sAb + (ar * APAD + a_kq * 4) * 4, \
                 A + (size_t)(m0 + ar) * EMB + (K0) + a_kq * 4); \
            const int br = it * 4 + b_kr; \
            cp16(sBb + (br * BPAD + b_nq * 4) * 4, \
                 W + (size_t)((K0) + br) * EMB + n0 + b_nq * 4); \
        } \
    } while (0)

    float acc[4][8][4];
    #pragma unroll
    for (int i = 0; i < 4; i++)
        #pragma unroll
        for (int j = 0; j < 8; j++)
            #pragma unroll
            for (int c = 0; c < 4; c++) acc[i][j][c] = 0.f;

    ISSUE_CHUNK(0, 0);
    cp_commit();

    for (int c = 0; c < EMB / 32; ++c) {
        if (c + 1 < EMB / 32) {
            ISSUE_CHUNK((c + 1) * 32, (c + 1) & 1);
            cp_commit();
        }
        if (c + 1 < EMB / 32) cp_wait<1>(); else cp_wait<0>();
        __syncthreads();

        const uint32_t* Ab = As + (c & 1) * ABUF;
        const uint32_t* Bb = Bs + (c & 1) * BBUF;

        #pragma unroll
        for (int ks = 0; ks < 4; ++ks) {
            const int kk = ks * 8 + qd;
            uint32_t af[4][4], bf[8][2];
            #pragma unroll
            for (int mt = 0; mt < 4; ++mt) {
                const int r = wm + mt * 16 + g;
                af[mt][0] = Ab[r * APAD + kk];
                af[mt][1] = Ab[(r + 8) * APAD + kk];
                af[mt][2] = Ab[r * APAD + kk + 4];
                af[mt][3] = Ab[(r + 8) * APAD + kk + 4];
            }
            #pragma unroll
            for (int nt = 0; nt < 8; ++nt) {
                const int n = wn + nt * 8 + g;
                bf[nt][0] = Bb[kk * BPAD + n];
                bf[nt][1] = Bb[(kk + 4) * BPAD + n];
            }
            #pragma unroll
            for (int mt = 0; mt < 4; ++mt)
                #pragma unroll
                for (int nt = 0; nt < 8; ++nt)
                    mma_tf32(acc[mt][nt], af[mt], bf[nt]);
        }
        __syncthreads();
    }
    #undef ISSUE_CHUNK

    #pragma unroll
    for (int mt = 0; mt < 4; ++mt) {
        #pragma unroll
        for (int ci = 0; ci < 2; ++ci) {
            const int m = m0 + wm + mt * 16 + g + ci * 8;
            #pragma unroll
            for (int nt = 0; nt < 8; ++nt) {
                const int nl = wn + nt * 8 + qd * 2;
                const int n  = n0 + nl;
                float vx = acc[mt][nt][ci * 2 + 0] + bias_s[nl];
                float vy = acc[mt][nt][ci * 2 + 1] + bias_s[nl + 1];
                if (MODE == 0) {
                    if (mat == 0) { vx *= QSCALE; vy *= QSCALE; }
                    const int b = m >> 11;
                    const int t = m & (SEQ - 1);
                    const int h = n >> 6;
                    const int d = n & (HSZ - 1);
                    uint32_t* dst = (mat == 0) ? g_q : (mat == 1) ? g_k : g_v;
                    uint2 o;
                    o.x = f2tf32(vx); o.y = f2tf32(vy);
                    *(uint2*)(dst + ((((size_t)b * NHEAD + h) * SEQ) + t) * HSZ + d) = o;
                } else {
                    float2 o; o.x = vx; o.y = vy;
                    *(float2*)(outp + (size_t)m * EMB + n) = o;
                }
            }
        }
    }
}

// =============================================================
// tensor-core causal flash attention v5: intra-CTA split-K.
// CTA: 128 queries, 256 threads = 8 warps. Warps 0-3: even K-tiles;
// warps 4-7 (same query groups): odd K-tiles. Private (m,l,O) per warp,
// exact online-softmax merge at the end. 4 K/V smem buffers.
// =============================================================
#define KSTRIDE 68
#define VSTRIDE 72
#define KVBUF_K (64 * KSTRIDE)
#define KVBUF_V (64 * VSTRIDE)
#define ATT_SMEM_BYTES ((4 * KVBUF_K + 4 * KVBUF_V) * 4)   // 143360

__global__ __launch_bounds__(256, 1) void attn_mma_kernel()
{
    extern __shared__ uint32_t sm[];
    uint32_t* KsBase = sm;                   // [4][KVBUF_K]
    uint32_t* VsBase = sm + 4 * KVBUF_K;     // [4][KVBUF_V]
    const int tid  = threadIdx.x;
    const int wid  = tid >> 5;
    const int lane = tid & 31;
    const int g    = lane >> 2;
    const int qd   = lane & 3;
    const int qwarp = wid & 3;               // query group 0..3
    const int half  = wid >> 2;              // 0: even tiles, 1: odd tiles

    const int bh = blockIdx.y;
    const int q0 = (gridDim.x - 1 - blockIdx.x) * 128;   // longest first
    const int wq = qwarp * 32;
    const int wrow = q0 + wq;
    const size_t base = (size_t)bh * SEQ * HSZ;
    const uint32_t* Qp = g_q + base;
    const uint32_t* Kp = g_k + base;
    const uint32_t* Vp = g_v + base;

    const uint32_t sK = (uint32_t)__cvta_generic_to_shared(KsBase);
    const uint32_t sV = (uint32_t)__cvta_generic_to_shared(VsBase);

    const int l_row = tid >> 4;   // 0..15
    const int l_c4  = tid & 15;

    #define ISSUE_TILE(KB, BUF) do { \
        const uint32_t sKb = sK + (BUF) * (KVBUF_K * 4); \
        const uint32_t sVb = sV + (BUF) * (KVBUF_V * 4); \
        _Pragma("unroll") \
        for (int it = 0; it < 4; ++it) { \
            const int row = it * 16 + l_row; \
            cp16(sKb + (row * KSTRIDE + l_c4 * 4) * 4, \
                 Kp + (size_t)((KB) + row) * HSZ + l_c4 * 4); \
            cp16(sVb + (row * VSTRIDE + l_c4 * 4) * 4, \
                 Vp + (size_t)((KB) + row) * HSZ + l_c4 * 4); \
        } \
    } while (0)

    // issue tile pair {0,1} into buffers 0,1 (ntile >= 2 always)
    ISSUE_TILE(0, 0);
    ISSUE_TILE(64, 1);
    cp_commit();

    // ---- stage Q (pre-scaled tf32 bits) in K buffers 2,3 (free until pair 1) ----
    #pragma unroll
    for (int it = 0; it < 8; ++it) {
        const int row = it * 16 + l_row;
        uint4 v = *(const uint4*)(Qp + (size_t)(q0 + row) * HSZ + l_c4 * 4);
        uint32_t* qdst = KsBase + ((row < 64) ? 2 : 3) * KVBUF_K;
        *(uint4*)&qdst[(row & 63) * KSTRIDE + l_c4 * 4] = v;
    }
    __syncthreads();

    uint32_t qf[2][8][4];
    {
        const uint32_t* qbuf = KsBase + ((wq < 64) ? 2 : 3) * KVBUF_K;
        #pragma unroll
        for (int mt = 0; mt < 2; ++mt) {
            const int r = (wq & 63) + mt * 16 + g;
            #pragma unroll
            for (int ks = 0; ks < 8; ++ks) {
                qf[mt][ks][0] = qbuf[r * KSTRIDE + ks * 8 + qd];
                qf[mt][ks][1] = qbuf[(r + 8) * KSTRIDE + ks * 8 + qd];
                qf[mt][ks][2] = qbuf[r * KSTRIDE + ks * 8 + qd + 4];
                qf[mt][ks][3] = qbuf[(r + 8) * KSTRIDE + ks * 8 + qd + 4];
            }
        }
    }
    __syncthreads();   // Q consumed before tile pair 1 overwrites buffers 2,3

    float of[2][8][4];
    #pragma unroll
    for (int mt = 0; mt < 2; ++mt)
        #pragma unroll
        for (int nt = 0; nt < 8; ++nt)
            #pragma unroll
            for (int c = 0; c < 4; ++c) of[mt][nt][c] = 0.f;
    float mx[4] = {-1e30f, -1e30f, -1e30f, -1e30f};
    float li[4] = {0.f, 0.f, 0.f, 0.f};

    const int ntile = (q0 >> 6) + 2;          // always even
    const int L0 = (g << 2) + (qd >> 1);

    for (int s = 0; s < ntile; s += 2) {
        if (s + 2 < ntile) {
            ISSUE_TILE((s + 2) * 64, (s + 2) & 3);
            ISSUE_TILE((s + 3) * 64, (s + 3) & 3);
            cp_commit();
            cp_wait<1>();
        } else {
            cp_wait<0>();
        }
        __syncthreads();   // pair {s, s+1} visible to all threads

        const int kt = s + half;
        const int kb = kt * 64;
        const bool active = (kb <= wrow + 31);
        if (active) {
            const uint32_t* Ks = KsBase + (kt & 3) * KVBUF_K;
            const uint32_t* Vs = VsBase + (kt & 3) * KVBUF_V;
            const bool need_mask = (kb + 63 > wrow);

            // ---- S = Q K^T (log2 domain) ----
            float sf[2][8][4];
            #pragma unroll
            for (int nt = 0; nt < 8; ++nt) {
                float s0[4] = {0.f, 0.f, 0.f, 0.f};
                float s1[4] = {0.f, 0.f, 0.f, 0.f};
                #pragma unroll
                for (int ks = 0; ks < 8; ++ks) {
                    uint32_t bf[2];
                    bf[0] = Ks[(nt * 8 + g) * KSTRIDE + ks * 8 + qd];
                    bf[1] = Ks[(nt * 8 + g) * KSTRIDE + ks * 8 + qd + 4];
                    mma_tf32(s0, qf[0][ks], bf);
                    mma_tf32(s1, qf[1][ks], bf);
                }
                if (need_mask) {
                    const int kl = kb + nt * 8 + 2 * qd;
                    const int r0 = wrow + g;
                    if (kl     > r0)      s0[0] = -1e30f;
                    if (kl + 1 > r0)      s0[1] = -1e30f;
                    if (kl     > r0 + 8)  s0[2] = -1e30f;
                    if (kl + 1 > r0 + 8)  s0[3] = -1e30f;
                    if (kl     > r0 + 16) s1[0] = -1e30f;
                    if (kl + 1 > r0 + 16) s1[1] = -1e30f;
                    if (kl     > r0 + 24) s1[2] = -1e30f;
                    if (kl + 1 > r0 + 24) s1[3] = -1e30f;
                }
                #pragma unroll
                for (int c = 0; c < 4; ++c) { sf[0][nt][c] = s0[c]; sf[1][nt][c] = s1[c]; }
            }

            // ---- online softmax (exp2 domain) ----
            #pragma unroll
            for (int mt = 0; mt < 2; ++mt) {
                float t0 = -1e30f, t1 = -1e30f;
                #pragma unroll
                for (int nt = 0; nt < 8; ++nt) {
                    t0 = fmaxf(t0, fmaxf(sf[mt][nt][0], sf[mt][nt][1]));
                    t1 = fmaxf(t1, fmaxf(sf[mt][nt][2], sf[mt][nt][3]));
                }
                t0 = fmaxf(t0, __shfl_xor_sync(0xffffffffu, t0, 1));
                t0 = fmaxf(t0, __shfl_xor_sync(0xffffffffu, t0, 2));
                t1 = fmaxf(t1, __shfl_xor_sync(0xffffffffu, t1, 1));
                t1 = fmaxf(t1, __shfl_xor_sync(0xffffffffu, t1, 2));

                const float mn0 = fmaxf(mx[mt * 2 + 0], t0);
                const float mn1 = fmaxf(mx[mt * 2 + 1], t1);
                const float cr0 = ex2(mx[mt * 2 + 0] - mn0);
                const float cr1 = ex2(mx[mt * 2 + 1] - mn1);
                mx[mt * 2 + 0] = mn0;
                mx[mt * 2 + 1] = mn1;

                float ps0 = 0.f, ps1 = 0.f;
                #pragma unroll
                for (int nt = 0; nt < 8; ++nt) {
                    sf[mt][nt][0] = ex2(sf[mt][nt][0] - mn0);
                    sf[mt][nt][1] = ex2(sf[mt][nt][1] - mn0);
                    sf[mt][nt][2] = ex2(sf[mt][nt][2] - mn1);
                    sf[mt][nt][3] = ex2(sf[mt][nt][3] - mn1);
                    ps0 += sf[mt][nt][0] + sf[mt][nt][1];
                    ps1 += sf[mt][nt][2] + sf[mt][nt][3];
                }
                ps0 += __shfl_xor_sync(0xffffffffu, ps0, 1);
                ps0 += __shfl_xor_sync(0xffffffffu, ps0, 2);
                ps1 += __shfl_xor_sync(0xffffffffu, ps1, 1);
                ps1 += __shfl_xor_sync(0xffffffffu, ps1, 2);
                li[mt * 2 + 0] = li[mt * 2 + 0] * cr0 + ps0;
                li[mt * 2 + 1] = li[mt * 2 + 1] * cr1 + ps1;

                #pragma unroll
                for (int nt = 0; nt < 8; ++nt) {
                    of[mt][nt][0] *= cr0; of[mt][nt][1] *= cr0;
                    of[mt][nt][2] *= cr1; of[mt][nt][3] *= cr1;
                }
            }

            // ---- O += P V (P -> A-frag via intra-quad shuffles) ----
            #pragma unroll
            for (int ks = 0; ks < 8; ++ks) {
                uint32_t af0[4], af1[4];
                #pragma unroll
                for (int mt = 0; mt < 2; ++mt) {
                    const uint32_t p0 = f2tf32(sf[mt][ks][0]);
                    const uint32_t p1 = f2tf32(sf[mt][ks][1]);
                    const uint32_t p2 = f2tf32(sf[mt][ks][2]);
                    const uint32_t p3 = f2tf32(sf[mt][ks][3]);
                    const uint32_t x0 = __shfl_sync(0xffffffffu, p0, L0);
                    const uint32_t x1 = __shfl_sync(0xffffffffu, p1, L0);
                    const uint32_t x2 = __shfl_sync(0xffffffffu, p2, L0);
                    const uint32_t x3 = __shfl_sync(0xffffffffu, p3, L0);
                    const uint32_t y0 = __shfl_sync(0xffffffffu, p0, L0 + 2);
                    const uint32_t y1 = __shfl_sync(0xffffffffu, p1, L0 + 2);
                    const uint32_t y2 = __shfl_sync(0xffffffffu, p2, L0 + 2);
                    const uint32_t y3 = __shfl_sync(0xffffffffu, p3, L0 + 2);
                    uint32_t* af = (mt == 0) ? af0 : af1;
                    af[0] = (qd & 1) ? x1 : x0;
                    af[1] = (qd & 1) ? x3 : x2;
                    af[2] = (qd & 1) ? y1 : y0;
                    af[3] = (qd & 1) ? y3 : y2;
                }
                #pragma unroll
                for (int nt = 0; nt < 8; ++nt) {
                    uint32_t bf[2];
                    bf[0] = Vs[(ks * 8 + qd) * VSTRIDE + nt * 8 + g];
                    bf[1] = Vs[(ks * 8 + qd + 4) * VSTRIDE + nt * 8 + g];
                    mma_tf32(of[0][nt], af0, bf);
                    mma_tf32(of[1][nt], af1, bf);
                }
            }
        }
        __syncthreads();   // compute done before next pair overwrites buffers
    }
    #undef ISSUE_TILE

    // ---- split-K merge: odd warps publish (O, m, l); even warps combine ----
    float* scratch = (float*)sm;   // KV buffers dead after last sync
    if (half == 1) {
        float* dst = scratch + ((size_t)(qwarp * 32 + lane)) * 72;
        #pragma unroll
        for (int mt = 0; mt < 2; ++mt)
            #pragma unroll
            for (int nt = 0; nt < 8; ++nt)
                #pragma unroll
                for (int c = 0; c < 4; ++c)
                    dst[mt * 32 + nt * 4 + c] = of[mt][nt][c];
        #pragma unroll
        for (int j = 0; j < 4; ++j) { dst[64 + j] = mx[j]; dst[68 + j] = li[j]; }
    }
    __syncthreads();

    if (half == 0) {
        const float* src = scratch + ((size_t)(qwarp * 32 + lane)) * 72;
        float ca[4], cb[4];
        #pragma unroll
        for (int j = 0; j < 4; ++j) {
            const float mb = src[64 + j];
            const float lb = src[68 + j];
            const float m  = fmaxf(mx[j], mb);
            ca[j] = ex2(mx[j] - m);
            cb[j] = ex2(mb - m);
            li[j] = li[j] * ca[j] + lb * cb[j];
        }
        #pragma unroll
        for (int mt = 0; mt < 2; ++mt)
            #pragma unroll
            for (int nt = 0; nt < 8; ++nt) {
                of[mt][nt][0] = of[mt][nt][0] * ca[mt * 2 + 0] + src[mt * 32 + nt * 4 + 0] * cb[mt * 2 + 0];
                of[mt][nt][1] = of[mt][nt][1] * ca[mt * 2 + 0] + src[mt * 32 + nt * 4 + 1] * cb[mt * 2 + 0];
                of[mt][nt][2] = of[mt][nt][2] * ca[mt * 2 + 1] + src[mt * 32 + nt * 4 + 2] * cb[mt * 2 + 1];
                of[mt][nt][3] = of[mt][nt][3] * ca[mt * 2 + 1] + src[mt * 32 + nt * 4 + 3] * cb[mt * 2 + 1];
            }

        // ---- epilogue: normalize, write y (tf32 bits, [B,T,C]) ----
        const int b = bh / NHEAD;
        const int h = bh % NHEAD;
        #pragma unroll
        for (int mt = 0; mt < 2; ++mt) {
            const float inv0 = 1.f / li[mt * 2 + 0];
            const float inv1 = 1.f / li[mt * 2 + 1];
            const int r0 = wrow + mt * 16 + g;
            uint32_t* y0 = g_y + ((size_t)b * SEQ + r0) * EMB + h * HSZ;
            uint32_t* y1 = g_y + ((size_t)b * SEQ + r0 + 8) * EMB + h * HSZ;
            #pragma unroll
            for (int nt = 0; nt < 8; ++nt) {
                uint2 o0, o1;
                o0.x = f2tf32(of[mt][nt][0] * inv0); o0.y = f2tf32(of[mt][nt][1] * inv0);
                o1.x = f2tf32(of[mt][nt][2] * inv1); o1.y = f2tf32(of[mt][nt][3] * inv1);
                *(uint2*)(y0 + nt * 8 + 2 * qd) = o0;
                *(uint2*)(y1 + nt * 8 + 2 * qd) = o1;
            }
        }
    }
}

// =============================================================
extern "C" void kernel_launch(void* const* d_in, const int* in_sizes, int n_in,
                              void* d_out, int out_size)
{
    const float* x  = (const float*)d_in[0];
    const float* Wq = (const float*)d_in[1];
    const float* bq = (const float*)d_in[2];
    const float* Wk = (const float*)d_in[3];
    const float* bk = (const float*)d_in[4];
    const float* Wv = (const float*)d_in[5];
    const float* bv = (const float*)d_in[6];
    const float* Wo = (const float*)d_in[7];
    const float* bo = (const float*)d_in[8];
    float* out = (float*)d_out;

    cudaFuncSetAttribute(gemm_kernel<0>, cudaFuncAttributeMaxDynamicSharedMemorySize,
                         GEMM_SMEM_BYTES);
    cudaFuncSetAttribute(gemm_kernel<1>, cudaFuncAttributeMaxDynamicSharedMemorySize,
                         GEMM_SMEM_BYTES);
    cudaFuncSetAttribute(attn_mma_kernel, cudaFuncAttributeMaxDynamicSharedMemorySize,
                         ATT_SMEM_BYTES);

    const int conv_blocks = (int)((NX + 4 * NW) / 256);
    convert_all_kernel<<<conv_blocks, 256>>>(x, Wq, Wk, Wv, Wo);

    dim3 qkv_grid(EMB / 128, MTOT / 128, 3);
    gemm_kernel<0><<<qkv_grid, 128, GEMM_SMEM_BYTES>>>(bq, bk, bv, nullptr);

    dim3 attn_grid(SEQ / 128, BATCH * NHEAD);   // (16, 64)
    attn_mma_kernel<<<attn_grid, 256, ATT_SMEM_BYTES>>>();

    dim3 oproj_grid(EMB / 128, MTOT / 128);
    gemm_kernel<1><<<oproj_grid, 128, GEMM_SMEM_BYTES>>>(bo, nullptr, nullptr, out);
}